// round 10
// baseline (speedup 1.0000x reference)
#include <cuda_runtime.h>
#include <cstddef>

#define N_NODES 8192
#define N_EDGES 262144
#define HID 128
#define FLATN (N_NODES * HID)   // 1048576
#define PF_FLOAT4 (4 * 1024 * 1024)   // 64 MB warmed into L2 (R6-proven size)

// ---------------- scratch (device globals) ----------------------------------
__device__ float g_h[FLATN];       // x@W buffer (reused for both layers)
__device__ float g_e1[FLATN];      // layer-1 output
__device__ int   g_degi[N_NODES];  // int degree histogram (edges only)
__device__ float g_dinv[N_NODES];
__device__ int   g_rowptr[N_NODES + 1];
__device__ int   g_cursor[N_NODES];
__device__ int   g_src[N_EDGES];   // CSR: source node per (target-sorted) edge
__device__ float g_acc[HID];       // fc1 partial-sum accumulator
__device__ float g_sink;           // prefetch sink (never actually written)

// ---------------- degree histogram over edge targets (2 edges/thread) -------
__global__ void k_deg(const int* __restrict__ col) {
    int t = blockIdx.x * blockDim.x + threadIdx.x;
    int2 c = __ldg((const int2*)col + t);
    atomicAdd(&g_degi[c.x], 1);
    atomicAdd(&g_degi[c.y], 1);
}

// ---------------- single-block scan: rowptr, cursor, dinv, acc=0 ------------
__global__ void __launch_bounds__(1024) k_scan() {
    const int t = threadIdx.x;
    int v[8];
    int s = 0;
    #pragma unroll
    for (int i = 0; i < 8; i++) {
        int d = g_degi[t * 8 + i];
        v[i] = s;
        s += d;
    }
    int lane = t & 31, warp = t >> 5;
    int inc = s;
    #pragma unroll
    for (int o = 1; o < 32; o <<= 1) {
        int n = __shfl_up_sync(0xFFFFFFFFu, inc, o);
        if (lane >= o) inc += n;
    }
    __shared__ int wsum[32];
    if (lane == 31) wsum[warp] = inc;
    __syncthreads();
    if (warp == 0) {
        int w = wsum[lane];
        #pragma unroll
        for (int o = 1; o < 32; o <<= 1) {
            int n = __shfl_up_sync(0xFFFFFFFFu, w, o);
            if (lane >= o) w += n;
        }
        wsum[lane] = w;
    }
    __syncthreads();
    int base = inc - s + (warp ? wsum[warp - 1] : 0);
    #pragma unroll
    for (int i = 0; i < 8; i++) {
        int p = base + v[i];
        g_rowptr[t * 8 + i] = p;
        g_cursor[t * 8 + i] = p;
    }
    if (t == 1023) g_rowptr[N_NODES] = N_EDGES;
    #pragma unroll
    for (int i = 0; i < 8; i++) {
        int n = t * 8 + i;
        g_dinv[n] = rsqrtf((float)(g_degi[n] + 1));
    }
    if (t < HID) g_acc[t] = 0.f;
}

// ---------------- CSR fill (2 edges/thread) ---------------------------------
__global__ void k_fill(const int* __restrict__ row, const int* __restrict__ col) {
    int t = blockIdx.x * blockDim.x + threadIdx.x;
    int2 c = __ldg((const int2*)col + t);
    int2 r = __ldg((const int2*)row + t);
    int p0 = atomicAdd(&g_cursor[c.x], 1);
    int p1 = atomicAdd(&g_cursor[c.y], 1);
    g_src[p0] = r.x;
    g_src[p1] = r.y;
}

// ---------------- L2 warm: touch first 64MB of fc1_w (MLP-4 body) -----------
__global__ void __launch_bounds__(256) k_prefetch(const float* __restrict__ w) {
    const float4* p = (const float4*)w;
    const int idx = blockIdx.x * blockDim.x + threadIdx.x;
    const int stride = gridDim.x * blockDim.x;
    float4 s0 = make_float4(0.f, 0.f, 0.f, 0.f);
    float4 s1 = s0, s2 = s0, s3 = s0;
    int i = idx;
    for (; i + 3 * stride < PF_FLOAT4; i += 4 * stride) {
        float4 v0 = __ldg(p + i);
        float4 v1 = __ldg(p + i + stride);
        float4 v2 = __ldg(p + i + 2 * stride);
        float4 v3 = __ldg(p + i + 3 * stride);
        s0.x += v0.x; s0.y += v0.y; s0.z += v0.z; s0.w += v0.w;
        s1.x += v1.x; s1.y += v1.y; s1.z += v1.z; s1.w += v1.w;
        s2.x += v2.x; s2.y += v2.y; s2.z += v2.z; s2.w += v2.w;
        s3.x += v3.x; s3.y += v3.y; s3.z += v3.z; s3.w += v3.w;
    }
    for (; i < PF_FLOAT4; i += stride) {
        float4 v = __ldg(p + i);
        s0.x += v.x; s0.y += v.y; s0.z += v.z; s0.w += v.w;
    }
    float s = s0.x + s0.y + s0.z + s0.w + s1.x + s1.y + s1.z + s1.w
            + s2.x + s2.y + s2.z + s2.w + s3.x + s3.y + s3.z + s3.w;
    if (__float_as_uint(s) == 0xDEADBEEFu) g_sink = s;   // keep loads live
}

// ---------------- GEMM: out[8192,128] = A[8192,128] @ W[128,128] ------------
#define GBM 32
#define WPITCH 132
__global__ void __launch_bounds__(256, 2) k_gemm(const float* __restrict__ A,
                                                 const float* __restrict__ W,
                                                 float* __restrict__ out) {
    extern __shared__ float smem[];
    float* Ws = smem;                       // [128][WPITCH]
    float* As = smem + 128 * WPITCH;        // [GBM][WPITCH]
    const int tid = threadIdx.x;

    #pragma unroll
    for (int i = tid; i < 128 * 32; i += 256) {
        int k = i >> 5, c4 = i & 31;
        *(float4*)&Ws[k * WPITCH + c4 * 4] = __ldg((const float4*)(W + k * HID) + c4);
    }
    const float* Ab = A + (size_t)blockIdx.x * GBM * HID;
    #pragma unroll
    for (int i = tid; i < GBM * 32; i += 256) {
        int r = i >> 5, c4 = i & 31;
        *(float4*)&As[r * WPITCH + c4 * 4] = __ldg((const float4*)(Ab + r * HID) + c4);
    }
    __syncthreads();

    const int tx = tid & 31;
    const int ty = tid >> 5;
    float acc[4][4];
    #pragma unroll
    for (int i = 0; i < 4; i++)
        #pragma unroll
        for (int j = 0; j < 4; j++) acc[i][j] = 0.f;

    const float* As0 = &As[(ty * 4 + 0) * WPITCH];
    const float* As1 = &As[(ty * 4 + 1) * WPITCH];
    const float* As2 = &As[(ty * 4 + 2) * WPITCH];
    const float* As3 = &As[(ty * 4 + 3) * WPITCH];

    #pragma unroll 8
    for (int k = 0; k < 128; k++) {
        float4 wv = *(const float4*)&Ws[k * WPITCH + tx * 4];
        float a0 = As0[k], a1 = As1[k], a2 = As2[k], a3 = As3[k];
        acc[0][0] += a0 * wv.x; acc[0][1] += a0 * wv.y; acc[0][2] += a0 * wv.z; acc[0][3] += a0 * wv.w;
        acc[1][0] += a1 * wv.x; acc[1][1] += a1 * wv.y; acc[1][2] += a1 * wv.z; acc[1][3] += a1 * wv.w;
        acc[2][0] += a2 * wv.x; acc[2][1] += a2 * wv.y; acc[2][2] += a2 * wv.z; acc[2][3] += a2 * wv.w;
        acc[3][0] += a3 * wv.x; acc[3][1] += a3 * wv.y; acc[3][2] += a3 * wv.z; acc[3][3] += a3 * wv.w;
    }
    #pragma unroll
    for (int i = 0; i < 4; i++) {
        float4 v = make_float4(acc[i][0], acc[i][1], acc[i][2], acc[i][3]);
        *(float4*)(out + (size_t)(blockIdx.x * GBM + ty * 4 + i) * HID + tx * 4) = v;
    }
}
#define GEMM_SMEM ((128 * WPITCH + GBM * WPITCH) * 4)

// ---------------- block-per-node neighbor accumulation (helper) --------------
__device__ __forceinline__ float gather_blk(const float* __restrict__ h,
                                            int node, int tid,
                                            float* s_nrm, int* s_off,
                                            float dc) {
    const int start = g_rowptr[node];
    const int end   = g_rowptr[node + 1];
    float acc0 = 0.f, acc1 = 0.f;
    for (int j0 = start; j0 < end; j0 += 128) {
        int m  = min(128, end - j0);
        int mp = (m + 7) & ~7;
        if (tid < m) {
            int s = __ldg(g_src + j0 + tid);
            s_nrm[tid] = g_dinv[s] * dc;
            s_off[tid] = s * HID;
        } else if (tid < mp) {
            s_nrm[tid] = 0.f;
            s_off[tid] = 0;
        }
        __syncthreads();
        for (int k = 0; k < mp; k += 8) {
            #pragma unroll
            for (int u = 0; u < 8; u += 2) {
                float n0 = s_nrm[k + u];
                float n1 = s_nrm[k + u + 1];
                float v0 = __ldg(h + s_off[k + u] + tid);
                float v1 = __ldg(h + s_off[k + u + 1] + tid);
                acc0 += n0 * v0;
                acc1 += n1 * v1;
            }
        }
        __syncthreads();
    }
    return acc0 + acc1;
}

// ---------------- gather (layer 1): e1[c] = relu(sum + self + bias) ---------
__global__ void __launch_bounds__(128) k_gather(const float* __restrict__ h,
                                                const float* __restrict__ b,
                                                float* __restrict__ out) {
    __shared__ float s_nrm[128];
    __shared__ int   s_off[128];
    const int node = blockIdx.x;
    const int tid  = threadIdx.x;
    const float dc = g_dinv[node];

    float acc = gather_blk(h, node, tid, s_nrm, s_off, dc);
    acc += dc * dc * __ldg(h + (size_t)node * HID + tid) + __ldg(b + tid);
    out[(size_t)node * HID + tid] = fmaxf(acc, 0.f);
}

// ---------------- gather (layer 2) fused with fc1 ---------------------------
// Phase 2 restructured: explicit groups of 8 front-batched LDG.128 into a
// register array, then the FMAs (per-thread MLP ~8, two accumulators).
__global__ void __launch_bounds__(128) k_gather_fc1(const float* __restrict__ h,
                                                    const float* __restrict__ b,
                                                    const float* __restrict__ fc1_w) {
    __shared__ float s_nrm[128];
    __shared__ int   s_off[128];
    __shared__ float fs[128];
    __shared__ float4 pp[4][32];
    const int node = blockIdx.x;
    const int tid  = threadIdx.x;
    const int lane = tid & 31;
    const int warp = tid >> 5;
    const float dc = g_dinv[node];

    float acc = gather_blk(h, node, tid, s_nrm, s_off, dc);
    acc += dc * dc * __ldg(h + (size_t)node * HID + tid) + __ldg(b + tid);
    fs[tid] = acc;
    __syncthreads();

    // Stream the node's 64KB slab: warp w handles rows j = i*4 + w.
    // 4 groups of 8: batch 8 independent LDG.128, then 8x4 FFMA.
    const float* Wb = fc1_w + (size_t)node * (HID * HID);
    float4 p0 = make_float4(0.f, 0.f, 0.f, 0.f);
    float4 p1 = p0;
    #pragma unroll
    for (int g = 0; g < 4; g++) {
        float4 w[8];
        #pragma unroll
        for (int u = 0; u < 8; u++) {
            int j = (g * 8 + u) * 4 + warp;
            w[u] = __ldcs((const float4*)(Wb + (size_t)j * HID) + lane);
        }
        #pragma unroll
        for (int u = 0; u < 8; u += 2) {
            float fa = fs[(g * 8 + u) * 4 + warp];
            float fb = fs[(g * 8 + u + 1) * 4 + warp];
            p0.x += fa * w[u].x;     p0.y += fa * w[u].y;
            p0.z += fa * w[u].z;     p0.w += fa * w[u].w;
            p1.x += fb * w[u + 1].x; p1.y += fb * w[u + 1].y;
            p1.z += fb * w[u + 1].z; p1.w += fb * w[u + 1].w;
        }
    }
    p0.x += p1.x; p0.y += p1.y; p0.z += p1.z; p0.w += p1.w;
    pp[warp][lane] = p0;
    __syncthreads();
    if (warp == 0) {
        float4 s0 = pp[0][lane], s1 = pp[1][lane], s2 = pp[2][lane], s3 = pp[3][lane];
        s0.x += s1.x + s2.x + s3.x;
        s0.y += s1.y + s2.y + s3.y;
        s0.z += s1.z + s2.z + s3.z;
        s0.w += s1.w + s2.w + s3.w;
        float* dst = &g_acc[lane * 4];
        asm volatile("red.global.add.v4.f32 [%0], {%1, %2, %3, %4};"
                     :: "l"(dst), "f"(s0.x), "f"(s0.y), "f"(s0.z), "f"(s0.w)
                     : "memory");
    }
}

// ---------------- tail: relu(fc1) -> fc2+relu -> fc3 -> scalar --------------
__global__ void k_tail(const float* __restrict__ fc1_b,
                       const float* __restrict__ fc2_w,
                       const float* __restrict__ fc2_b,
                       const float* __restrict__ fc3_w,
                       const float* __restrict__ fc3_b,
                       float* __restrict__ out) {
    __shared__ float h1[HID];
    __shared__ float red[4];
    int tid = threadIdx.x;
    h1[tid] = fmaxf(g_acc[tid] + fc1_b[tid], 0.f);
    __syncthreads();
    float s = 0.f;
    #pragma unroll 8
    for (int k = 0; k < HID; k++) s += h1[k] * fc2_w[k * HID + tid];
    float h2 = fmaxf(s + fc2_b[tid], 0.f);
    float p = h2 * fc3_w[tid];
    #pragma unroll
    for (int o = 16; o; o >>= 1) p += __shfl_xor_sync(0xFFFFFFFFu, p, o);
    if ((tid & 31) == 0) red[tid >> 5] = p;
    __syncthreads();
    if (tid == 0) out[0] = red[0] + red[1] + red[2] + red[3] + fc3_b[0];
}

// ---------------- launch ----------------------------------------------------
extern "C" void kernel_launch(void* const* d_in, const int* in_sizes, int n_in,
                              void* d_out, int out_size) {
    const float* x      = (const float*)d_in[0];
    const int*   ei     = (const int*)d_in[1];     // [2, N_EDGES] row-major
    const float* W1     = (const float*)d_in[2];
    const float* b1     = (const float*)d_in[3];
    const float* W2     = (const float*)d_in[4];
    const float* b2     = (const float*)d_in[5];
    const float* fc1_w  = (const float*)d_in[6];
    const float* fc1_b  = (const float*)d_in[7];
    const float* fc2_w  = (const float*)d_in[8];
    const float* fc2_b  = (const float*)d_in[9];
    const float* fc3_w  = (const float*)d_in[10];
    const float* fc3_b  = (const float*)d_in[11];
    float* out = (float*)d_out;

    const int* row = ei;               // sources
    const int* colv = ei + N_EDGES;    // targets

    float *p_h, *p_e1;
    int *p_degi;
    cudaGetSymbolAddress((void**)&p_h,    g_h);
    cudaGetSymbolAddress((void**)&p_e1,   g_e1);
    cudaGetSymbolAddress((void**)&p_degi, g_degi);

    cudaFuncSetAttribute(k_gemm, cudaFuncAttributeMaxDynamicSharedMemorySize, GEMM_SMEM);

    // One-time handle creation (host resources only; no device allocation).
    static cudaStream_t s2 = nullptr, s3 = nullptr;
    static cudaEvent_t ev_root = nullptr, ev_pre = nullptr, ev_pf = nullptr;
    if (!s2) {
        cudaStreamCreateWithFlags(&s2, cudaStreamNonBlocking);
        cudaStreamCreateWithFlags(&s3, cudaStreamNonBlocking);
        cudaEventCreateWithFlags(&ev_root, cudaEventDisableTiming);
        cudaEventCreateWithFlags(&ev_pre,  cudaEventDisableTiming);
        cudaEventCreateWithFlags(&ev_pf,   cudaEventDisableTiming);
    }

    // Fork: preproc on s2, fc1_w L2-warm on s3, gemm1 on the main stream.
    cudaEventRecord(ev_root, 0);
    cudaStreamWaitEvent(s2, ev_root, 0);
    cudaStreamWaitEvent(s3, ev_root, 0);

    cudaMemsetAsync(p_degi, 0, N_NODES * sizeof(int), s2);
    k_deg<<<N_EDGES / 2 / 256, 256, 0, s2>>>(colv);
    k_scan<<<1, 1024, 0, s2>>>();
    k_fill<<<N_EDGES / 2 / 256, 256, 0, s2>>>(row, colv);
    cudaEventRecord(ev_pre, s2);

    k_prefetch<<<1024, 256, 0, s3>>>(fc1_w);
    cudaEventRecord(ev_pf, s3);

    k_gemm<<<N_NODES / GBM, 256, GEMM_SMEM>>>(x, W1, p_h);

    // Join preproc before gather1.
    cudaStreamWaitEvent(0, ev_pre, 0);
    k_gather<<<N_NODES, 128>>>(p_h, b1, p_e1);

    k_gemm<<<N_NODES / GBM, 256, GEMM_SMEM>>>(p_e1, W2, p_h);

    // Join prefetch before the fused stream kernel.
    cudaStreamWaitEvent(0, ev_pf, 0);
    k_gather_fc1<<<N_NODES, 128>>>(p_h, b2, fc1_w);

    k_tail<<<1, 128>>>(fc1_b, fc2_w, fc2_b, fc3_w, fc3_b, out);
}

// round 11
// speedup vs baseline: 1.2912x; 1.2912x over previous
#include <cuda_runtime.h>
#include <cstddef>

#define N_NODES 8192
#define N_EDGES 262144
#define HID 128
#define FLATN (N_NODES * HID)   // 1048576
#define PF_FLOAT4 (4 * 1024 * 1024)   // 64 MB warmed into L2 (R6-proven)

// ---------------- scratch (device globals) ----------------------------------
__device__ float g_h[FLATN];       // x@W buffer (reused for both layers)
__device__ float g_e1[FLATN];      // layer-1 output
__device__ int   g_degi[N_NODES];  // int degree histogram (edges only)
__device__ float g_dinv[N_NODES];
__device__ int   g_rowptr[N_NODES + 1];
__device__ int   g_cursor[N_NODES];
__device__ int   g_src[N_EDGES];   // CSR: source node per (target-sorted) edge
__device__ float g_acc[HID];       // fc1 partial-sum accumulator
__device__ float g_sink;           // prefetch sink (never actually written)

// ---------------- degree histogram over edge targets (2 edges/thread) -------
__global__ void k_deg(const int* __restrict__ col) {
    int t = blockIdx.x * blockDim.x + threadIdx.x;
    int2 c = __ldg((const int2*)col + t);
    atomicAdd(&g_degi[c.x], 1);
    atomicAdd(&g_degi[c.y], 1);
}

// ---------------- single-block scan: rowptr, cursor, dinv, acc=0 ------------
__global__ void __launch_bounds__(1024) k_scan() {
    const int t = threadIdx.x;
    int v[8];
    int s = 0;
    #pragma unroll
    for (int i = 0; i < 8; i++) {
        int d = g_degi[t * 8 + i];
        v[i] = s;
        s += d;
    }
    int lane = t & 31, warp = t >> 5;
    int inc = s;
    #pragma unroll
    for (int o = 1; o < 32; o <<= 1) {
        int n = __shfl_up_sync(0xFFFFFFFFu, inc, o);
        if (lane >= o) inc += n;
    }
    __shared__ int wsum[32];
    if (lane == 31) wsum[warp] = inc;
    __syncthreads();
    if (warp == 0) {
        int w = wsum[lane];
        #pragma unroll
        for (int o = 1; o < 32; o <<= 1) {
            int n = __shfl_up_sync(0xFFFFFFFFu, w, o);
            if (lane >= o) w += n;
        }
        wsum[lane] = w;
    }
    __syncthreads();
    int base = inc - s + (warp ? wsum[warp - 1] : 0);
    #pragma unroll
    for (int i = 0; i < 8; i++) {
        int p = base + v[i];
        g_rowptr[t * 8 + i] = p;
        g_cursor[t * 8 + i] = p;
    }
    if (t == 1023) g_rowptr[N_NODES] = N_EDGES;
    #pragma unroll
    for (int i = 0; i < 8; i++) {
        int n = t * 8 + i;
        g_dinv[n] = rsqrtf((float)(g_degi[n] + 1));
    }
    if (t < HID) g_acc[t] = 0.f;
}

// ---------------- CSR fill (2 edges/thread) ---------------------------------
__global__ void k_fill(const int* __restrict__ row, const int* __restrict__ col) {
    int t = blockIdx.x * blockDim.x + threadIdx.x;
    int2 c = __ldg((const int2*)col + t);
    int2 r = __ldg((const int2*)row + t);
    int p0 = atomicAdd(&g_cursor[c.x], 1);
    int p1 = atomicAdd(&g_cursor[c.y], 1);
    g_src[p0] = r.x;
    g_src[p1] = r.y;
}

// ---------------- L2 warm: touch first 64MB of fc1_w (R6 body) --------------
__global__ void __launch_bounds__(256) k_prefetch(const float* __restrict__ w) {
    const float4* p = (const float4*)w;
    int idx = blockIdx.x * blockDim.x + threadIdx.x;
    int stride = gridDim.x * blockDim.x;
    float s = 0.f;
    for (int i = idx; i < PF_FLOAT4; i += stride) {
        float4 v = __ldg(p + i);
        s += v.x + v.y + v.z + v.w;
    }
    if (__float_as_uint(s) == 0xDEADBEEFu) g_sink = s;   // keep loads live
}

// ---------------- GEMM: out[8192,128] = A[8192,128] @ W[128,128] ------------
#define GBM 32
#define WPITCH 132
__global__ void __launch_bounds__(256, 2) k_gemm(const float* __restrict__ A,
                                                 const float* __restrict__ W,
                                                 float* __restrict__ out) {
    extern __shared__ float smem[];
    float* Ws = smem;                       // [128][WPITCH]
    float* As = smem + 128 * WPITCH;        // [GBM][WPITCH]
    const int tid = threadIdx.x;

    #pragma unroll
    for (int i = tid; i < 128 * 32; i += 256) {
        int k = i >> 5, c4 = i & 31;
        *(float4*)&Ws[k * WPITCH + c4 * 4] = __ldg((const float4*)(W + k * HID) + c4);
    }
    const float* Ab = A + (size_t)blockIdx.x * GBM * HID;
    #pragma unroll
    for (int i = tid; i < GBM * 32; i += 256) {
        int r = i >> 5, c4 = i & 31;
        *(float4*)&As[r * WPITCH + c4 * 4] = __ldg((const float4*)(Ab + r * HID) + c4);
    }
    __syncthreads();

    const int tx = tid & 31;
    const int ty = tid >> 5;
    float acc[4][4];
    #pragma unroll
    for (int i = 0; i < 4; i++)
        #pragma unroll
        for (int j = 0; j < 4; j++) acc[i][j] = 0.f;

    const float* As0 = &As[(ty * 4 + 0) * WPITCH];
    const float* As1 = &As[(ty * 4 + 1) * WPITCH];
    const float* As2 = &As[(ty * 4 + 2) * WPITCH];
    const float* As3 = &As[(ty * 4 + 3) * WPITCH];

    #pragma unroll 8
    for (int k = 0; k < 128; k++) {
        float4 wv = *(const float4*)&Ws[k * WPITCH + tx * 4];
        float a0 = As0[k], a1 = As1[k], a2 = As2[k], a3 = As3[k];
        acc[0][0] += a0 * wv.x; acc[0][1] += a0 * wv.y; acc[0][2] += a0 * wv.z; acc[0][3] += a0 * wv.w;
        acc[1][0] += a1 * wv.x; acc[1][1] += a1 * wv.y; acc[1][2] += a1 * wv.z; acc[1][3] += a1 * wv.w;
        acc[2][0] += a2 * wv.x; acc[2][1] += a2 * wv.y; acc[2][2] += a2 * wv.z; acc[2][3] += a2 * wv.w;
        acc[3][0] += a3 * wv.x; acc[3][1] += a3 * wv.y; acc[3][2] += a3 * wv.z; acc[3][3] += a3 * wv.w;
    }
    #pragma unroll
    for (int i = 0; i < 4; i++) {
        float4 v = make_float4(acc[i][0], acc[i][1], acc[i][2], acc[i][3]);
        *(float4*)(out + (size_t)(blockIdx.x * GBM + ty * 4 + i) * HID + tx * 4) = v;
    }
}
#define GEMM_SMEM ((128 * WPITCH + GBM * WPITCH) * 4)

// ---------------- block-per-node neighbor accumulation (helper) --------------
// Used by k_gather with 128 threads (R6-identical).
__device__ __forceinline__ float gather_blk(const float* __restrict__ h,
                                            int node, int tid,
                                            float* s_nrm, int* s_off,
                                            float dc) {
    const int start = g_rowptr[node];
    const int end   = g_rowptr[node + 1];
    float acc0 = 0.f, acc1 = 0.f;
    for (int j0 = start; j0 < end; j0 += 128) {
        int m  = min(128, end - j0);
        int mp = (m + 7) & ~7;
        if (tid < m) {
            int s = __ldg(g_src + j0 + tid);
            s_nrm[tid] = g_dinv[s] * dc;
            s_off[tid] = s * HID;
        } else if (tid < mp) {
            s_nrm[tid] = 0.f;
            s_off[tid] = 0;
        }
        __syncthreads();
        for (int k = 0; k < mp; k += 8) {
            #pragma unroll
            for (int u = 0; u < 8; u += 2) {
                float n0 = s_nrm[k + u];
                float n1 = s_nrm[k + u + 1];
                float v0 = __ldg(h + s_off[k + u] + tid);
                float v1 = __ldg(h + s_off[k + u + 1] + tid);
                acc0 += n0 * v0;
                acc1 += n1 * v1;
            }
        }
        __syncthreads();
    }
    return acc0 + acc1;
}

// ---------------- gather (layer 1): e1[c] = relu(sum + self + bias) ---------
__global__ void __launch_bounds__(128) k_gather(const float* __restrict__ h,
                                                const float* __restrict__ b,
                                                float* __restrict__ out) {
    __shared__ float s_nrm[128];
    __shared__ int   s_off[128];
    const int node = blockIdx.x;
    const int tid  = threadIdx.x;
    const float dc = g_dinv[node];

    float acc = gather_blk(h, node, tid, s_nrm, s_off, dc);
    acc += dc * dc * __ldg(h + (size_t)node * HID + tid) + __ldg(b + tid);
    out[(size_t)node * HID + tid] = fmaxf(acc, 0.f);
}

// ---------------- gather (layer 2) fused with fc1 (256 threads) -------------
// Warps 0-3: gather phase (R6-identical inner loop); warps 4-7 idle through
// the uniform sync skeleton. Then ALL 8 warps co-stream the 64KB slab
// (warp w: rows jj*8+w) with the R6-proven unroll-8 stream body.
__global__ void __launch_bounds__(256) k_gather_fc1(const float* __restrict__ h,
                                                    const float* __restrict__ b,
                                                    const float* __restrict__ fc1_w) {
    __shared__ float s_nrm[128];
    __shared__ int   s_off[128];
    __shared__ float fs[128];
    __shared__ float4 pp[8][32];
    const int node = blockIdx.x;
    const int tid  = threadIdx.x;
    const int lane = tid & 31;
    const int warp = tid >> 5;
    const float dc = g_dinv[node];

    // Gather phase: uniform loop skeleton for all 256 threads; only tid<128
    // stage and compute (same instruction pattern as R6 for those warps).
    {
        const int start = g_rowptr[node];
        const int end   = g_rowptr[node + 1];
        float acc0 = 0.f, acc1 = 0.f;
        for (int j0 = start; j0 < end; j0 += 128) {
            int m  = min(128, end - j0);
            int mp = (m + 7) & ~7;
            if (tid < m) {
                int s = __ldg(g_src + j0 + tid);
                s_nrm[tid] = g_dinv[s] * dc;
                s_off[tid] = s * HID;
            } else if (tid < mp) {
                s_nrm[tid] = 0.f;
                s_off[tid] = 0;
            }
            __syncthreads();
            if (tid < 128) {
                for (int k = 0; k < mp; k += 8) {
                    #pragma unroll
                    for (int u = 0; u < 8; u += 2) {
                        float n0 = s_nrm[k + u];
                        float n1 = s_nrm[k + u + 1];
                        float v0 = __ldg(h + s_off[k + u] + tid);
                        float v1 = __ldg(h + s_off[k + u + 1] + tid);
                        acc0 += n0 * v0;
                        acc1 += n1 * v1;
                    }
                }
            }
            __syncthreads();
        }
        if (tid < 128) {
            float a = acc0 + acc1;
            a += dc * dc * __ldg(h + (size_t)node * HID + tid) + __ldg(b + tid);
            fs[tid] = a;
        }
    }
    __syncthreads();

    // Stream phase: 8 warps, warp w rows j = jj*8 + w (16 iters, unroll 8).
    const float* Wb = fc1_w + (size_t)node * (HID * HID);
    float4 p = make_float4(0.f, 0.f, 0.f, 0.f);
    #pragma unroll 8
    for (int jj = 0; jj < 16; jj++) {
        int j = jj * 8 + warp;
        float fj = fs[j];
        float4 w = __ldcs((const float4*)(Wb + (size_t)j * HID) + lane);
        p.x += fj * w.x; p.y += fj * w.y; p.z += fj * w.z; p.w += fj * w.w;
    }
    pp[warp][lane] = p;
    __syncthreads();
    if (warp == 0) {
        float4 s0 = pp[0][lane];
        #pragma unroll
        for (int w = 1; w < 8; w++) {
            float4 t = pp[w][lane];
            s0.x += t.x; s0.y += t.y; s0.z += t.z; s0.w += t.w;
        }
        float* dst = &g_acc[lane * 4];
        asm volatile("red.global.add.v4.f32 [%0], {%1, %2, %3, %4};"
                     :: "l"(dst), "f"(s0.x), "f"(s0.y), "f"(s0.z), "f"(s0.w)
                     : "memory");
    }
}

// ---------------- tail: relu(fc1) -> fc2+relu -> fc3 -> scalar --------------
__global__ void k_tail(const float* __restrict__ fc1_b,
                       const float* __restrict__ fc2_w,
                       const float* __restrict__ fc2_b,
                       const float* __restrict__ fc3_w,
                       const float* __restrict__ fc3_b,
                       float* __restrict__ out) {
    __shared__ float h1[HID];
    __shared__ float red[4];
    int tid = threadIdx.x;
    h1[tid] = fmaxf(g_acc[tid] + fc1_b[tid], 0.f);
    __syncthreads();
    float s = 0.f;
    #pragma unroll 8
    for (int k = 0; k < HID; k++) s += h1[k] * fc2_w[k * HID + tid];
    float h2 = fmaxf(s + fc2_b[tid], 0.f);
    float p = h2 * fc3_w[tid];
    #pragma unroll
    for (int o = 16; o; o >>= 1) p += __shfl_xor_sync(0xFFFFFFFFu, p, o);
    if ((tid & 31) == 0) red[tid >> 5] = p;
    __syncthreads();
    if (tid == 0) out[0] = red[0] + red[1] + red[2] + red[3] + fc3_b[0];
}

// ---------------- launch ----------------------------------------------------
extern "C" void kernel_launch(void* const* d_in, const int* in_sizes, int n_in,
                              void* d_out, int out_size) {
    const float* x      = (const float*)d_in[0];
    const int*   ei     = (const int*)d_in[1];     // [2, N_EDGES] row-major
    const float* W1     = (const float*)d_in[2];
    const float* b1     = (const float*)d_in[3];
    const float* W2     = (const float*)d_in[4];
    const float* b2     = (const float*)d_in[5];
    const float* fc1_w  = (const float*)d_in[6];
    const float* fc1_b  = (const float*)d_in[7];
    const float* fc2_w  = (const float*)d_in[8];
    const float* fc2_b  = (const float*)d_in[9];
    const float* fc3_w  = (const float*)d_in[10];
    const float* fc3_b  = (const float*)d_in[11];
    float* out = (float*)d_out;

    const int* row = ei;               // sources
    const int* colv = ei + N_EDGES;    // targets

    float *p_h, *p_e1;
    int *p_degi;
    cudaGetSymbolAddress((void**)&p_h,    g_h);
    cudaGetSymbolAddress((void**)&p_e1,   g_e1);
    cudaGetSymbolAddress((void**)&p_degi, g_degi);

    cudaFuncSetAttribute(k_gemm, cudaFuncAttributeMaxDynamicSharedMemorySize, GEMM_SMEM);

    // One-time handle creation (host resources only; no device allocation).
    static cudaStream_t s2 = nullptr, s3 = nullptr;
    static cudaEvent_t ev_root = nullptr, ev_pre = nullptr, ev_pf = nullptr;
    if (!s2) {
        cudaStreamCreateWithFlags(&s2, cudaStreamNonBlocking);
        cudaStreamCreateWithFlags(&s3, cudaStreamNonBlocking);
        cudaEventCreateWithFlags(&ev_root, cudaEventDisableTiming);
        cudaEventCreateWithFlags(&ev_pre,  cudaEventDisableTiming);
        cudaEventCreateWithFlags(&ev_pf,   cudaEventDisableTiming);
    }

    // Fork: preproc on s2, fc1_w L2-warm on s3, gemm1 on the main stream.
    cudaEventRecord(ev_root, 0);
    cudaStreamWaitEvent(s2, ev_root, 0);
    cudaStreamWaitEvent(s3, ev_root, 0);

    cudaMemsetAsync(p_degi, 0, N_NODES * sizeof(int), s2);
    k_deg<<<N_EDGES / 2 / 256, 256, 0, s2>>>(colv);
    k_scan<<<1, 1024, 0, s2>>>();
    k_fill<<<N_EDGES / 2 / 256, 256, 0, s2>>>(row, colv);
    cudaEventRecord(ev_pre, s2);

    k_prefetch<<<1024, 256, 0, s3>>>(fc1_w);
    cudaEventRecord(ev_pf, s3);

    k_gemm<<<N_NODES / GBM, 256, GEMM_SMEM>>>(x, W1, p_h);

    // Join preproc before gather1.
    cudaStreamWaitEvent(0, ev_pre, 0);
    k_gather<<<N_NODES, 128>>>(p_h, b1, p_e1);

    k_gemm<<<N_NODES / GBM, 256, GEMM_SMEM>>>(p_e1, W2, p_h);

    // Join prefetch before the fused stream kernel.
    cudaStreamWaitEvent(0, ev_pf, 0);
    k_gather_fc1<<<N_NODES, 256>>>(p_h, b2, fc1_w);

    k_tail<<<1, 128>>>(fc1_b, fc2_w, fc2_b, fc3_w, fc3_b, out);
}